// round 3
// baseline (speedup 1.0000x reference)
#include <cuda_runtime.h>

#define BB 32
#define TT 512
#define DD 384
#define ML 4096
#define D4 (DD / 4)   // 96 float4 per row

// Scratch: token index per (batch, frame); -1 => invalid (beyond total)
__device__ int g_tokmap[BB * ML];

// Kernel A: per-batch inclusive scan of durations, scatter token ids into
// g_tokmap, write mel_pos (as float) directly into output tail.
__global__ void lr_scan_scatter(const int* __restrict__ dur,
                                float* __restrict__ mel_pos_out) {
    __shared__ int s[TT];
    __shared__ int s_total;
    const int b = blockIdx.x;
    const int t = threadIdx.x;

    const int d = dur[b * TT + t];
    s[t] = d;
    __syncthreads();

    // Kogge-Stone inclusive scan over 512 elements
    #pragma unroll
    for (int off = 1; off < TT; off <<= 1) {
        int v = (t >= off) ? s[t - off] : 0;
        __syncthreads();
        s[t] += v;
        __syncthreads();
    }
    const int cum = s[t];
    if (t == TT - 1) s_total = cum;
    __syncthreads();
    const int total = s_total;

    // Fill invalid entries + mel_pos. Valid tokmap entries are fully covered
    // by the scatter below.
    for (int f = t; f < ML; f += TT) {
        const bool valid = f < total;
        if (!valid) g_tokmap[b * ML + f] = -1;
        mel_pos_out[b * ML + f] = valid ? (float)(f + 1) : 0.0f;
    }

    // Scatter: token t owns frames [cum-d, cum). d < 8 so at most 7 writes.
    const int start = cum - d;
    for (int f = start; f < cum; ++f) {
        g_tokmap[b * ML + f] = t;
    }
}

// Kernel B: one 96-thread block per 8-frame group. threadIdx.x == c4.
// Two int4 tokmap loads (broadcast), 8 independent x gathers (MLP=8),
// 8 streaming stores.
__global__ __launch_bounds__(96) void lr_gather(const float4* __restrict__ x,
                                                float4* __restrict__ out) {
    const int c4 = threadIdx.x;          // 0..95
    const int go = blockIdx.x;           // 0..BB*ML/8-1
    const int b  = go >> 9;              // ML/8 = 512 groups per batch
    const int f0 = (go & 511) << 3;

    const int4* tm = reinterpret_cast<const int4*>(&g_tokmap[b * ML + f0]);
    const int4 ta = __ldg(&tm[0]);
    const int4 tb = __ldg(&tm[1]);

    const float4* xb = x + (size_t)b * TT * D4 + c4;
    const float4 z = make_float4(0.0f, 0.0f, 0.0f, 0.0f);

    float4 v0 = (ta.x >= 0) ? __ldg(xb + ta.x * D4) : z;
    float4 v1 = (ta.y >= 0) ? __ldg(xb + ta.y * D4) : z;
    float4 v2 = (ta.z >= 0) ? __ldg(xb + ta.z * D4) : z;
    float4 v3 = (ta.w >= 0) ? __ldg(xb + ta.w * D4) : z;
    float4 v4 = (tb.x >= 0) ? __ldg(xb + tb.x * D4) : z;
    float4 v5 = (tb.y >= 0) ? __ldg(xb + tb.y * D4) : z;
    float4 v6 = (tb.z >= 0) ? __ldg(xb + tb.z * D4) : z;
    float4 v7 = (tb.w >= 0) ? __ldg(xb + tb.w * D4) : z;

    float4* o = out + (size_t)(b * ML + f0) * D4 + c4;
    __stcs(o,          v0);
    __stcs(o + D4,     v1);
    __stcs(o + 2 * D4, v2);
    __stcs(o + 3 * D4, v3);
    __stcs(o + 4 * D4, v4);
    __stcs(o + 5 * D4, v5);
    __stcs(o + 6 * D4, v6);
    __stcs(o + 7 * D4, v7);
}

extern "C" void kernel_launch(void* const* d_in, const int* in_sizes, int n_in,
                              void* d_out, int out_size) {
    const float* x   = (const float*)d_in[0];
    const int*   dur = (const int*)d_in[1];

    float* out = (float*)d_out;                 // [B, ML, D] f32
    float* mel = out + (size_t)BB * ML * DD;    // [B, ML] written as float

    lr_scan_scatter<<<BB, TT>>>(dur, mel);

    lr_gather<<<BB * (ML / 8), 96>>>((const float4*)x, (float4*)out);
}

// round 4
// speedup vs baseline: 1.0366x; 1.0366x over previous
#include <cuda_runtime.h>

#define BB 32
#define TT 512
#define DD 384
#define ML 4096
#define D4 (DD / 4)   // 96 float4 per row

// Per-token packed (start<<4 | dur), start <= 3584 fits 12 bits, dur < 8.
__device__ int g_startd[BB * TT];
__device__ int g_total[BB];

// Kernel A: per-batch inclusive scan of durations; emit packed start/dur,
// per-batch total, and mel_pos (as float) into the output tail.
__global__ void lr_scan(const int* __restrict__ dur,
                        float* __restrict__ mel_pos_out) {
    __shared__ int s[TT];
    __shared__ int s_total;
    const int b = blockIdx.x;
    const int t = threadIdx.x;

    const int d = dur[b * TT + t];
    s[t] = d;
    __syncthreads();

    // Kogge-Stone inclusive scan over 512 elements
    #pragma unroll
    for (int off = 1; off < TT; off <<= 1) {
        int v = (t >= off) ? s[t - off] : 0;
        __syncthreads();
        s[t] += v;
        __syncthreads();
    }
    const int cum = s[t];
    if (t == TT - 1) { s_total = cum; g_total[b] = cum; }

    g_startd[b * TT + t] = ((cum - d) << 4) | d;
    __syncthreads();
    const int total = s_total;

    for (int f = t; f < ML; f += TT) {
        mel_pos_out[b * ML + f] = (f < total) ? (float)(f + 1) : 0.0f;
    }
}

// Kernel B: token-scatter + zero-fill, 96 threads (threadIdx.x == c4).
//  blocks [0, BB*TT/4)          : 4 tokens each. x loads are address-static
//                                 (blockIdx-derived) -> issue immediately,
//                                 no dependent gather chain. Each x row read
//                                 once; stored dur times to consecutive rows.
//  blocks [BB*TT/4, +BB*ML/8)   : 8 frames each; write zeros where f >= total.
#define NTOKBLK (BB * TT / 4)     // 4096
__global__ __launch_bounds__(96) void lr_scatter(const float4* __restrict__ x,
                                                 float4* __restrict__ out) {
    const int c4 = threadIdx.x;

    if (blockIdx.x < NTOKBLK) {
        const int tb = blockIdx.x;
        const int b  = tb >> 7;            // TT/4 = 128 token-groups per batch
        const int t0 = (tb & 127) << 2;

        // Independent streaming loads, issued before the startd load resolves.
        const float4* xr = x + ((size_t)b * TT + t0) * D4 + c4;
        const float4 v0 = __ldg(xr);
        const float4 v1 = __ldg(xr + D4);
        const float4 v2 = __ldg(xr + 2 * D4);
        const float4 v3 = __ldg(xr + 3 * D4);

        const int4 sd = __ldg(reinterpret_cast<const int4*>(&g_startd[b * TT + t0]));

        float4* ob = out + (size_t)b * ML * D4 + c4;
        {
            const int dd = sd.x & 15; float4* o = ob + (size_t)(sd.x >> 4) * D4;
            for (int j = 0; j < dd; ++j) __stcs(o + (size_t)j * D4, v0);
        }
        {
            const int dd = sd.y & 15; float4* o = ob + (size_t)(sd.y >> 4) * D4;
            for (int j = 0; j < dd; ++j) __stcs(o + (size_t)j * D4, v1);
        }
        {
            const int dd = sd.z & 15; float4* o = ob + (size_t)(sd.z >> 4) * D4;
            for (int j = 0; j < dd; ++j) __stcs(o + (size_t)j * D4, v2);
        }
        {
            const int dd = sd.w & 15; float4* o = ob + (size_t)(sd.w >> 4) * D4;
            for (int j = 0; j < dd; ++j) __stcs(o + (size_t)j * D4, v3);
        }
    } else {
        const int zb = blockIdx.x - NTOKBLK;
        const int b  = zb >> 9;            // ML/8 = 512 frame-groups per batch
        const int f0 = (zb & 511) << 3;

        const int total = __ldg(&g_total[b]);
        if (f0 + 8 <= total) return;       // fully valid: covered by scatter

        const float4 z = make_float4(0.0f, 0.0f, 0.0f, 0.0f);
        float4* o = out + ((size_t)b * ML + f0) * D4 + c4;
        const int jlo = (total > f0) ? (total - f0) : 0;
        #pragma unroll
        for (int j = 0; j < 8; ++j) {
            if (j >= jlo) __stcs(o + (size_t)j * D4, z);
        }
    }
}

extern "C" void kernel_launch(void* const* d_in, const int* in_sizes, int n_in,
                              void* d_out, int out_size) {
    const float* x   = (const float*)d_in[0];
    const int*   dur = (const int*)d_in[1];

    float* out = (float*)d_out;                 // [B, ML, D] f32
    float* mel = out + (size_t)BB * ML * DD;    // [B, ML] written as float

    lr_scan<<<BB, TT>>>(dur, mel);

    const int nblk = NTOKBLK + BB * (ML / 8);   // 4096 + 16384
    lr_scatter<<<nblk, 96>>>((const float4*)x, (float4*)out);
}

// round 5
// speedup vs baseline: 1.0516x; 1.0145x over previous
#include <cuda_runtime.h>

#define BB 32
#define TT 512
#define DD 384
#define ML 4096
#define D4 (DD / 4)   // 96 float4 per row

// Per-token packed (start<<4 | dur); start <= 3584 fits 12 bits, dur < 8.
__device__ int g_startd[BB * TT];
__device__ int g_total[BB];

// Kernel A: scan ONLY (shfl warp scan, 2 barriers). 512 thr = 16 warps.
__global__ __launch_bounds__(TT) void lr_scan(const int* __restrict__ dur) {
    __shared__ int s_wsum[16];
    const int b = blockIdx.x;
    const int t = threadIdx.x;
    const int w = t >> 5;
    const int lane = t & 31;

    const int d = dur[b * TT + t];

    // warp inclusive scan
    int c = d;
    #pragma unroll
    for (int off = 1; off < 32; off <<= 1) {
        int v = __shfl_up_sync(0xffffffffu, c, off);
        if (lane >= off) c += v;
    }
    if (lane == 31) s_wsum[w] = c;
    __syncthreads();

    // warp 0 scans the 16 warp sums
    if (w == 0) {
        int ws = (lane < 16) ? s_wsum[lane] : 0;
        #pragma unroll
        for (int off = 1; off < 16; off <<= 1) {
            int v = __shfl_up_sync(0xffffffffu, ws, off);
            if (lane >= off) ws += v;
        }
        if (lane < 16) s_wsum[lane] = ws;
    }
    __syncthreads();

    const int cum = c + (w ? s_wsum[w - 1] : 0);
    g_startd[b * TT + t] = ((cum - d) << 4) | d;
    if (t == TT - 1) g_total[b] = cum;
}

// Kernel B: token-scatter + zero-fill + mel_pos. 96 threads (tid == c4).
//  blocks [0, NTOKBLK): 4 tokens each; address-static x loads (MLP=4),
//                       each row stored dur times to consecutive frames.
//  blocks [NTOKBLK, +BB*ML/16): 16-frame chunk; write mel_pos (4 float4
//                       from threads 0..3), zero-fill rows where f >= total.
#define NTOKBLK (BB * TT / 4)     // 4096
#define NZROWS  16
__global__ __launch_bounds__(96) void lr_scatter(const float4* __restrict__ x,
                                                 float4* __restrict__ out,
                                                 float4* __restrict__ mel4) {
    const int c4 = threadIdx.x;

    if (blockIdx.x < NTOKBLK) {
        const int tb = blockIdx.x;
        const int b  = tb >> 7;            // TT/4 = 128 token-groups per batch
        const int t0 = (tb & 127) << 2;

        const float4* xr = x + ((size_t)b * TT + t0) * D4 + c4;
        const float4 v0 = __ldg(xr);
        const float4 v1 = __ldg(xr + D4);
        const float4 v2 = __ldg(xr + 2 * D4);
        const float4 v3 = __ldg(xr + 3 * D4);

        const int4 sd = __ldg(reinterpret_cast<const int4*>(&g_startd[b * TT + t0]));

        float4* ob = out + (size_t)b * ML * D4 + c4;
        {
            const int dd = sd.x & 15; float4* o = ob + (size_t)(sd.x >> 4) * D4;
            for (int j = 0; j < dd; ++j) __stcs(o + (size_t)j * D4, v0);
        }
        {
            const int dd = sd.y & 15; float4* o = ob + (size_t)(sd.y >> 4) * D4;
            for (int j = 0; j < dd; ++j) __stcs(o + (size_t)j * D4, v1);
        }
        {
            const int dd = sd.z & 15; float4* o = ob + (size_t)(sd.z >> 4) * D4;
            for (int j = 0; j < dd; ++j) __stcs(o + (size_t)j * D4, v2);
        }
        {
            const int dd = sd.w & 15; float4* o = ob + (size_t)(sd.w >> 4) * D4;
            for (int j = 0; j < dd; ++j) __stcs(o + (size_t)j * D4, v3);
        }
    } else {
        const int zb = blockIdx.x - NTOKBLK;
        const int b  = zb >> 8;            // ML/16 = 256 chunks per batch
        const int f0 = (zb & 255) << 4;

        const int total = __ldg(&g_total[b]);

        // mel_pos for this 16-frame chunk: threads 0..3 each write a float4.
        if (c4 < 4) {
            const int f = f0 + c4 * 4;
            float4 m;
            m.x = (f     < total) ? (float)(f + 1) : 0.0f;
            m.y = (f + 1 < total) ? (float)(f + 2) : 0.0f;
            m.z = (f + 2 < total) ? (float)(f + 3) : 0.0f;
            m.w = (f + 3 < total) ? (float)(f + 4) : 0.0f;
            mel4[(b * ML + f) >> 2] = m;
        }

        if (f0 + NZROWS <= total) return;  // fully valid: scatter covers it

        const float4 z = make_float4(0.0f, 0.0f, 0.0f, 0.0f);
        float4* o = out + ((size_t)b * ML + f0) * D4 + c4;
        const int jlo = (total > f0) ? (total - f0) : 0;
        #pragma unroll
        for (int j = 0; j < NZROWS; ++j) {
            if (j >= jlo) __stcs(o + (size_t)j * D4, z);
        }
    }
}

extern "C" void kernel_launch(void* const* d_in, const int* in_sizes, int n_in,
                              void* d_out, int out_size) {
    const float* x   = (const float*)d_in[0];
    const int*   dur = (const int*)d_in[1];

    float* out = (float*)d_out;                 // [B, ML, D] f32
    float* mel = out + (size_t)BB * ML * DD;    // [B, ML] written as float

    lr_scan<<<BB, TT>>>(dur);

    const int nblk = NTOKBLK + BB * (ML / NZROWS);  // 4096 + 8192
    lr_scatter<<<nblk, 96>>>((const float4*)x, (float4*)out, (float4*)mel);
}

// round 7
// speedup vs baseline: 1.1174x; 1.0626x over previous
#include <cuda_runtime.h>

#define BB 32
#define TT 512
#define DD 384
#define ML 4096
#define D4 (DD / 4)        // 96 float4 per row
#define NTOKBLK (BB * TT / 4)   // 4096 token blocks (4 tokens each)
#define NZROWS  8
#define NZBLK   (BB * (ML / NZROWS))  // 16384 frame blocks

// Block-wide sum of per-thread 'v' over 96 threads (3 warps). All threads
// get the result. ~2 shfl stages + one smem round.
__device__ __forceinline__ int block_sum96(int v, int* s3) {
    #pragma unroll
    for (int off = 16; off > 0; off >>= 1)
        v += __shfl_down_sync(0xffffffffu, v, off);
    const int w = threadIdx.x >> 5;
    if ((threadIdx.x & 31) == 0) s3[w] = v;
    __syncthreads();
    return s3[0] + s3[1] + s3[2];
}

// Single fused kernel. 96 threads per block (threadIdx.x == c4).
//  blocks [0, NTOKBLK): 4 tokens; address-static x loads issued first,
//    per-batch prefix over dur[0..t0) recomputed in-block (L1/L2 hits,
//    hidden under x-load latency). Each x row stored dur times.
//  blocks [NTOKBLK, +NZBLK): 8-frame chunk; total = full-batch reduce;
//    mel_pos from threads 0..1; zero-fill rows with f >= total.
__global__ __launch_bounds__(96) void lr_fused(const float4* __restrict__ x,
                                               const int*    __restrict__ dur,
                                               float4* __restrict__ out,
                                               float4* __restrict__ mel4) {
    __shared__ int s3[3];
    const int c4 = threadIdx.x;

    if (blockIdx.x < NTOKBLK) {
        const int tb = blockIdx.x;
        const int b  = tb >> 7;             // TT/4 = 128 token-groups/batch
        const int t0 = (tb & 127) << 2;

        // Streaming x loads: addresses depend only on blockIdx -> issue now.
        const float4* xr = x + ((size_t)b * TT + t0) * D4 + c4;
        const float4 v0 = __ldg(xr);
        const float4 v1 = __ldg(xr + D4);
        const float4 v2 = __ldg(xr + 2 * D4);
        const float4 v3 = __ldg(xr + 3 * D4);

        // Prefix over dur[b][0..t0) + this group's 4 durations (overlapped).
        const int4* dq = reinterpret_cast<const int4*>(dur + b * TT);
        const int nq = t0 >> 2;             // 0..127 int4s before this group
        int part = 0;
        for (int q = c4; q < nq; q += 96) {
            const int4 u = __ldg(&dq[q]);
            part += u.x + u.y + u.z + u.w;
        }
        const int4 dv = __ldg(&dq[nq]);     // d0..d3
        const int prefix = block_sum96(part, s3);

        const int s0 = prefix;
        const int s1 = s0 + dv.x;
        const int s2 = s1 + dv.y;
        const int s3s = s2 + dv.z;

        float4* ob = out + (size_t)b * ML * D4 + c4;
        {
            float4* o = ob + (size_t)s0 * D4;
            for (int j = 0; j < dv.x; ++j) __stcs(o + (size_t)j * D4, v0);
        }
        {
            float4* o = ob + (size_t)s1 * D4;
            for (int j = 0; j < dv.y; ++j) __stcs(o + (size_t)j * D4, v1);
        }
        {
            float4* o = ob + (size_t)s2 * D4;
            for (int j = 0; j < dv.z; ++j) __stcs(o + (size_t)j * D4, v2);
        }
        {
            float4* o = ob + (size_t)s3s * D4;
            for (int j = 0; j < dv.w; ++j) __stcs(o + (size_t)j * D4, v3);
        }
    } else {
        const int zb = blockIdx.x - NTOKBLK;
        const int b  = zb >> 9;             // ML/8 = 512 chunks per batch
        const int f0 = (zb & 511) << 3;

        // total = sum of all 512 durations (128 int4s; L1/L2 hits).
        const int4* dq = reinterpret_cast<const int4*>(dur + b * TT);
        int part = 0;
        {
            const int4 u = __ldg(&dq[c4]);
            part = u.x + u.y + u.z + u.w;
            if (c4 < 32) {
                const int4 u2 = __ldg(&dq[c4 + 96]);
                part += u2.x + u2.y + u2.z + u2.w;
            }
        }
        const int total = block_sum96(part, s3);

        // mel_pos for these 8 frames: threads 0..1 each write a float4.
        if (c4 < 2) {
            const int f = f0 + c4 * 4;
            float4 m;
            m.x = (f     < total) ? (float)(f + 1) : 0.0f;
            m.y = (f + 1 < total) ? (float)(f + 2) : 0.0f;
            m.z = (f + 2 < total) ? (float)(f + 3) : 0.0f;
            m.w = (f + 3 < total) ? (float)(f + 4) : 0.0f;
            mel4[(b * ML + f) >> 2] = m;
        }

        if (f0 + NZROWS <= total) return;   // fully valid: scatter covers it

        const float4 z = make_float4(0.0f, 0.0f, 0.0f, 0.0f);
        float4* o = out + ((size_t)b * ML + f0) * D4 + c4;
        const int jlo = (total > f0) ? (total - f0) : 0;
        #pragma unroll
        for (int j = 0; j < NZROWS; ++j) {
            if (j >= jlo) __stcs(o + (size_t)j * D4, z);
        }
    }
}

extern "C" void kernel_launch(void* const* d_in, const int* in_sizes, int n_in,
                              void* d_out, int out_size) {
    const float* x   = (const float*)d_in[0];
    const int*   dur = (const int*)d_in[1];

    float* out = (float*)d_out;                 // [B, ML, D] f32
    float* mel = out + (size_t)BB * ML * DD;    // [B, ML] written as float

    lr_fused<<<NTOKBLK + NZBLK, 96>>>((const float4*)x, dur,
                                      (float4*)out, (float4*)mel);
}